// round 9
// baseline (speedup 1.0000x reference)
#include <cuda_runtime.h>
#include <cuda_fp16.h>
#include <math.h>
#include <stdint.h>

#define NB     4096
#define NROWS  8192
#define DDIM   128
#define NCTA   1056        // tiles (p,q): 256-row x 128-col, 2p <= q <= 63
#define E2LOG2 2.885390081777927f   // 2 * log2(e)

// ---------------- static scratch (no allocations allowed) ----------------
__device__ __half g_hi[NROWS * DDIM];
__device__ float  g_rowsum[NROWS];
__device__ float  g_pos[NROWS];
__device__ float  g_self[NROWS];

// ---------------- helpers ----------------
__device__ __forceinline__ uint32_t smem_u32(const void* p) {
    uint32_t a;
    asm("{ .reg .u64 t; cvta.to.shared.u64 t, %1; cvt.u32.u64 %0, t; }"
        : "=r"(a) : "l"(p));
    return a;
}
__device__ __forceinline__ void ldsm4(uint32_t* r, uint32_t addr) {
    asm volatile("ldmatrix.sync.aligned.m8n8.x4.shared.b16 {%0,%1,%2,%3}, [%4];"
                 : "=r"(r[0]), "=r"(r[1]), "=r"(r[2]), "=r"(r[3]) : "r"(addr));
}
__device__ __forceinline__ void mma_h(uint32_t* d, const uint32_t* a,
                                      uint32_t b0, uint32_t b1) {
    asm volatile("mma.sync.aligned.m16n8k16.row.col.f16.f16.f16.f16 "
                 "{%0,%1}, {%2,%3,%4,%5}, {%6,%7}, {%0,%1};"
                 : "+r"(d[0]), "+r"(d[1])
                 : "r"(a[0]), "r"(a[1]), "r"(a[2]), "r"(a[3]), "r"(b0), "r"(b1));
}
__device__ __forceinline__ uint32_t hmul2(uint32_t a, uint32_t b) {
    uint32_t o; asm("mul.rn.f16x2 %0, %1, %2;" : "=r"(o) : "r"(a), "r"(b)); return o;
}
__device__ __forceinline__ uint32_t hadd2(uint32_t a, uint32_t b) {
    uint32_t o; asm("add.rn.f16x2 %0, %1, %2;" : "=r"(o) : "r"(a), "r"(b)); return o;
}
__device__ __forceinline__ uint32_t hex2(uint32_t a) {
    uint32_t o; asm("ex2.approx.f16x2 %0, %1;" : "=r"(o) : "r"(a)); return o;
}
__device__ __forceinline__ float2 h2f2(uint32_t h) {
    __half2 v = *reinterpret_cast<__half2*>(&h);
    return __half22float2(v);
}
__device__ __forceinline__ void cp16(uint32_t dst, const void* src) {
    asm volatile("cp.async.cg.shared.global [%0], [%1], 16;"
                 :: "r"(dst), "l"(src) : "memory");
}
#define CP_COMMIT() asm volatile("cp.async.commit_group;" ::: "memory")
#define CP_WAIT0()  asm volatile("cp.async.wait_group 0;" ::: "memory")

// smem: A tile 256 rows + B tile 128 rows, pitch 272 (17x16B, conflict-free ldmatrix)
#define PITCH    272
#define SM_A     0
#define SM_B     (256 * PITCH)
#define SM_ROWS  (384 * PITCH)
#define SM_COLS  (SM_ROWS + 256 * 4)
#define SMEM_SZ  (SM_COLS + 128 * 4)

// ---------------- K1: normalize rows (warp per row) + positives/self ----------------
__global__ void __launch_bounds__(256) k_norm(const float* __restrict__ p1,
                                              const float* __restrict__ p2,
                                              float* __restrict__ out) {
    int w    = (blockIdx.x * blockDim.x + threadIdx.x) >> 5;   // row 0..NROWS-1
    int lane = threadIdx.x & 31;
    if (w >= NROWS) return;
    if (w == 0 && lane == 0) out[0] = 0.0f;

    if (w < NB) {
        float4 v1 = *(const float4*)(p1 + (size_t)w * DDIM + lane * 4);
        float4 v2 = *(const float4*)(p2 + (size_t)w * DDIM + lane * 4);
        float ss1 = v1.x*v1.x + v1.y*v1.y + v1.z*v1.z + v1.w*v1.w;
        float ss2 = v2.x*v2.x + v2.y*v2.y + v2.z*v2.z + v2.w*v2.w;
        float cx  = v1.x*v2.x + v1.y*v2.y + v1.z*v2.z + v1.w*v2.w;
#pragma unroll
        for (int o = 16; o; o >>= 1) {
            ss1 += __shfl_xor_sync(0xffffffffu, ss1, o);
            ss2 += __shfl_xor_sync(0xffffffffu, ss2, o);
            cx  += __shfl_xor_sync(0xffffffffu, cx,  o);
        }
        float inv1 = 1.0f / fmaxf(sqrtf(ss1), 1e-12f);
        float inv2 = 1.0f / fmaxf(sqrtf(ss2), 1e-12f);
        v1.x *= inv1; v1.y *= inv1; v1.z *= inv1; v1.w *= inv1;
        size_t base = (size_t)w * DDIM + lane * 4;
        *(__half2*)(g_hi + base)     = __floats2half2_rn(v1.x, v1.y);
        *(__half2*)(g_hi + base + 2) = __floats2half2_rn(v1.z, v1.w);
        if (lane == 0) {
            float pos = cx * inv1 * inv2;
            g_pos[w] = pos;             g_pos[w + NB] = pos;
            g_self[w]      = ss1 * inv1 * inv1;
            g_self[w + NB] = ss2 * inv2 * inv2;
            g_rowsum[w] = 0.0f;         g_rowsum[w + NB] = 0.0f;
        }
    } else {
        float4 v = *(const float4*)(p2 + (size_t)(w - NB) * DDIM + lane * 4);
        float ss = v.x*v.x + v.y*v.y + v.z*v.z + v.w*v.w;
#pragma unroll
        for (int o = 16; o; o >>= 1) ss += __shfl_xor_sync(0xffffffffu, ss, o);
        float inv = 1.0f / fmaxf(sqrtf(ss), 1e-12f);
        v.x *= inv; v.y *= inv; v.z *= inv; v.w *= inv;
        size_t base = (size_t)w * DDIM + lane * 4;
        *(__half2*)(g_hi + base)     = __floats2half2_rn(v.x, v.y);
        *(__half2*)(g_hi + base + 2) = __floats2half2_rn(v.z, v.w);
    }
}

// ---------------- K2: HMMA(f16) sim-GEMM, 256x128 tiles over triangle ----------------
extern __shared__ char smem_raw[];

__global__ void __launch_bounds__(256, 2) k_gemm() {
    const int tid  = threadIdx.x;
    const int wid  = tid >> 5;
    const int lane = tid & 31;

    // decode (p, q): S(2m)=m^2+m, S(2m+1)=(m+1)^2
    const int t = blockIdx.x;
    int m0 = (int)sqrtf((float)t + 0.5f);
    while (m0 * m0 > t) --m0;
    while ((m0 + 1) * (m0 + 1) <= t) ++m0;
    const int q  = (t >= m0 * m0 + m0) ? 2 * m0 : 2 * m0 - 1;
    const int Sq = (q & 1) ? ((q + 1) / 2) * ((q + 1) / 2)
                           : (q / 2) * (q / 2) + q / 2;
    const int p  = t - Sq;
    // ctype: 0 = all off-diag, 1 = lower half diag (2p+1==q), 2 = upper diag (2p==q)
    const int ctype = (2 * p == q) ? 2 : ((2 * p + 1 == q) ? 1 : 0);
    const int r0 = 256 * p;      // A rows r0..r0+255
    const int c0 = 128 * q;      // B rows c0..c0+127

    const uint32_t sb = smem_u32(smem_raw);
    float* smrows = (float*)(smem_raw + SM_ROWS);
    float* smcols = (float*)(smem_raw + SM_COLS);
    smrows[tid] = 0.0f;
    if (tid < 128) smcols[tid] = 0.0f;

    // async load A (256 rows) + B (128 rows): 384 rows x 16 segs of 16B
#pragma unroll
    for (int it = 0; it < 24; ++it) {
        int idx = tid + it * 256;
        int row = idx >> 4;
        int seg = idx & 15;
        int grow = (row < 256) ? r0 + row : c0 + (row - 256);
        cp16(sb + (uint32_t)(row * PITCH + seg * 16),
             g_hi + (size_t)grow * DDIM + seg * 8);
    }
    CP_COMMIT();
    CP_WAIT0();
    __syncthreads();

    const int wm = wid >> 1;          // 0..3 -> rows 64*wm
    const int wn = wid & 1;           // 0..1 -> cols 64*wn
    const bool credit_row = !(ctype == 2 && wm >= 2);
    const bool credit_col = (ctype == 0) || (ctype == 1 && wm < 2);

    const uint32_t a_base = sb +
        (uint32_t)((64 * wm + (lane & 15)) * PITCH + (lane >> 4) * 16);
    const int brow = 64 * wn + (lane & 7) + ((lane >> 4) << 3);
    const uint32_t b_base = sb + SM_B +
        (uint32_t)(brow * PITCH + ((lane >> 3) & 1) * 16);

    uint32_t acc[4][8][2];            // f16x2 accumulators, 64x64 warp tile
#pragma unroll
    for (int mi = 0; mi < 4; ++mi)
#pragma unroll
        for (int nj = 0; nj < 8; ++nj) { acc[mi][nj][0] = 0u; acc[mi][nj][1] = 0u; }

#pragma unroll
    for (int kk = 0; kk < 8; ++kk) {
        uint32_t b[4][4];
#pragma unroll
        for (int nq = 0; nq < 4; ++nq)
            ldsm4(b[nq], b_base + nq * 16 * PITCH + kk * 32);
#pragma unroll
        for (int mi = 0; mi < 4; ++mi) {
            uint32_t a[4];
            ldsm4(a, a_base + kk * 32 + mi * 16 * PITCH);
#pragma unroll
            for (int nq = 0; nq < 4; ++nq) {
                mma_h(acc[mi][2 * nq],     a, b[nq][0], b[nq][1]);
                mma_h(acc[mi][2 * nq + 1], a, b[nq][2], b[nq][3]);
            }
        }
    }

    // exp(2*sim) = exp2(E2LOG2 * sim), f16x2 (2 exps per MUFU)
    const __half2 sc2h = __float2half2_rn(E2LOG2);
    const uint32_t sc2 = *reinterpret_cast<const uint32_t*>(&sc2h);
#pragma unroll
    for (int mi = 0; mi < 4; ++mi)
#pragma unroll
        for (int nj = 0; nj < 8; ++nj) {
            acc[mi][nj][0] = hex2(hmul2(acc[mi][nj][0], sc2));
            acc[mi][nj][1] = hex2(hmul2(acc[mi][nj][1], sc2));
        }

    // row partial sums: f16x2 tree over nj, quad shfl-reduce, 1 atomic/row/quad
    if (credit_row) {
        const int rbase = 64 * wm + (lane >> 2);
#pragma unroll
        for (int mi = 0; mi < 4; ++mi) {
            uint32_t hlo = hadd2(hadd2(hadd2(acc[mi][0][0], acc[mi][1][0]),
                                       hadd2(acc[mi][2][0], acc[mi][3][0])),
                                 hadd2(hadd2(acc[mi][4][0], acc[mi][5][0]),
                                       hadd2(acc[mi][6][0], acc[mi][7][0])));
            uint32_t hhi = hadd2(hadd2(hadd2(acc[mi][0][1], acc[mi][1][1]),
                                       hadd2(acc[mi][2][1], acc[mi][3][1])),
                                 hadd2(hadd2(acc[mi][4][1], acc[mi][5][1]),
                                       hadd2(acc[mi][6][1], acc[mi][7][1])));
            float2 flo = h2f2(hlo), fhi = h2f2(hhi);
            float slo = flo.x + flo.y;
            float shi = fhi.x + fhi.y;
            slo += __shfl_xor_sync(0xffffffffu, slo, 1);
            slo += __shfl_xor_sync(0xffffffffu, slo, 2);
            shi += __shfl_xor_sync(0xffffffffu, shi, 1);
            shi += __shfl_xor_sync(0xffffffffu, shi, 2);
            if ((lane & 3) == 0) {
                atomicAdd(&smrows[rbase + 16 * mi],     slo);
                atomicAdd(&smrows[rbase + 16 * mi + 8], shi);
            }
        }
    }

    // column partial sums (credit the transpose rows)
    if (credit_col) {
#pragma unroll
        for (int nj = 0; nj < 8; ++nj) {
            uint32_t v2 = hadd2(hadd2(hadd2(acc[0][nj][0], acc[0][nj][1]),
                                      hadd2(acc[1][nj][0], acc[1][nj][1])),
                                hadd2(hadd2(acc[2][nj][0], acc[2][nj][1]),
                                      hadd2(acc[3][nj][0], acc[3][nj][1])));
            float2 f = h2f2(v2);
            float ve = f.x, vo = f.y;
            ve += __shfl_down_sync(0xffffffffu, ve, 16);
            ve += __shfl_down_sync(0xffffffffu, ve, 8);
            ve += __shfl_down_sync(0xffffffffu, ve, 4);
            vo += __shfl_down_sync(0xffffffffu, vo, 16);
            vo += __shfl_down_sync(0xffffffffu, vo, 8);
            vo += __shfl_down_sync(0xffffffffu, vo, 4);
            if (lane < 4) {
                atomicAdd(&smcols[64 * wn + 8 * nj + lane * 2],     ve);
                atomicAdd(&smcols[64 * wn + 8 * nj + lane * 2 + 1], vo);
            }
        }
    }
    __syncthreads();
    atomicAdd(&g_rowsum[r0 + tid], smrows[tid]);          // rows (0 where uncredited)
    if (tid < 128 && ctype != 2) atomicAdd(&g_rowsum[c0 + tid], smcols[tid]);
}

// ---------------- K3: final reduction (8 blocks + atomic) ----------------
__global__ void __launch_bounds__(1024) k_final(float* __restrict__ out) {
    __shared__ float red[1024];
    int tid = threadIdx.x;
    int r = blockIdx.x * 1024 + tid;
    float den = g_rowsum[r] - exp2f(E2LOG2 * g_self[r]);
    red[tid] = __logf(den) - 2.0f * g_pos[r];
    __syncthreads();
#pragma unroll
    for (int o = 512; o; o >>= 1) {
        if (tid < o) red[tid] += red[tid + o];
        __syncthreads();
    }
    if (tid == 0) atomicAdd(out, red[0] * (1.0f / (float)NROWS));
}

// ---------------- launcher ----------------
extern "C" void kernel_launch(void* const* d_in, const int* in_sizes, int n_in,
                              void* d_out, int out_size) {
    const float* p1 = (const float*)d_in[0];
    const float* p2 = (const float*)d_in[1];
    float* out = (float*)d_out;

    cudaFuncSetAttribute(k_gemm, cudaFuncAttributeMaxDynamicSharedMemorySize, SMEM_SZ);

    k_norm<<<NROWS / 8, 256>>>(p1, p2, out);
    k_gemm<<<NCTA, 256, SMEM_SZ>>>();
    k_final<<<NROWS / 1024, 1024>>>(out);
}